// round 12
// baseline (speedup 1.0000x reference)
#include <cuda_runtime.h>
#include <cuda_bf16.h>
#include <stdint.h>

#define N1 8192
#define N2 8192
#define D  1024
#define C  128
#define NTY 8
#define KE3 3072            // 3*D  expanded K (same-type GEMM)
#define KC3 384             // 3*C  expanded K (cross GEMM)

#define STAGES      3
#define CHUNK_K     64                        // bf16 k per chunk
#define A_STAGE     (128 * 128)               // 128 rows x 128B = 16 KB
#define B_STAGE     (256 * 128)               // 256 rows x 128B = 32 KB
#define STAGE_BYTES (A_STAGE + B_STAGE)       // 48 KB
#define SMEM_BYTES  (STAGES * STAGE_BYTES)    // 144 KB

// ---------------- device scratch (static: no runtime allocation) ----------------
__device__ __align__(1024) __nv_bfloat16 g_ft1p[(size_t)N1 * KE3];  // perm order, (hi,hi,lo)
__device__ __align__(1024) __nv_bfloat16 g_ft2p[(size_t)N2 * KE3];  // perm order, (hi,lo,hi)
__device__ __align__(1024) __nv_bfloat16 g_sl1x[(size_t)N1 * KC3];  // orig order, (hi,hi,lo)
__device__ __align__(1024) __nv_bfloat16 g_sl2x[(size_t)N2 * KC3];  // orig order, (hi,lo,hi)
__device__ int g_perm1[N1], g_perm2[N2];
__device__ int g_start1[NTY], g_cnt1[NTY];
__device__ int g_start2[NTY], g_cnt2[NTY];
__device__ int g_tilePrefix[NTY + 1];
__device__ int g_totalTiles;
__device__ int g_is64;

// ---------------- small PTX helpers (base ISA, compute_103-safe) ----------------
__device__ __forceinline__ uint32_t smem_u32(const void* p) {
    uint32_t a;
    asm("{ .reg .u64 t; cvta.to.shared.u64 t, %1; cvt.u32.u64 %0, t; }" : "=r"(a) : "l"(p));
    return a;
}
__device__ __forceinline__ void cp16(uint32_t s, const void* g) {
    asm volatile("cp.async.cg.shared.global [%0], [%1], 16;" :: "r"(s), "l"(g));
}
#define CP_COMMIT() asm volatile("cp.async.commit_group;" ::: "memory")
#define CP_WAIT1()  asm volatile("cp.async.wait_group 1;" ::: "memory")

__device__ __forceinline__ void ldsm4(uint32_t r[4], uint32_t addr) {
    asm volatile("ldmatrix.sync.aligned.m8n8.x4.shared.b16 {%0,%1,%2,%3}, [%4];"
                 : "=r"(r[0]), "=r"(r[1]), "=r"(r[2]), "=r"(r[3]) : "r"(addr));
}
__device__ __forceinline__ void mma16816(float c[4], const uint32_t a[4],
                                         uint32_t b0, uint32_t b1) {
    asm volatile("mma.sync.aligned.m16n8k16.row.col.f32.bf16.bf16.f32 "
                 "{%0,%1,%2,%3}, {%4,%5,%6,%7}, {%8,%9}, {%0,%1,%2,%3};"
                 : "+f"(c[0]), "+f"(c[1]), "+f"(c[2]), "+f"(c[3])
                 : "r"(a[0]), "r"(a[1]), "r"(a[2]), "r"(a[3]), "r"(b0), "r"(b1));
}
// swizzled smem address: rows 128B, 16B quads, quad' = quad ^ (row & 7)
__device__ __forceinline__ uint32_t swz(uint32_t base, int row, int quad) {
    return base + row * 128 + ((quad ^ (row & 7)) << 4);
}

// ---------------- dtype detection (int64 vs silently-downgraded int32) ----------
__global__ void detect_kernel(const int* __restrict__ tyraw) {
    __shared__ int sAny;
    if (threadIdx.x == 0) sAny = 0;
    __syncthreads();
    int any = 0;
    for (int i = threadIdx.x; i < 4096; i += blockDim.x) any |= (tyraw[2 * i + 1] != 0);
    if (any) atomicOr(&sAny, 1);
    __syncthreads();
    if (threadIdx.x == 0) g_is64 = sAny ? 0 : 1;
}
__device__ __forceinline__ int load_type(const void* ty, int i, int is64) {
    int t = is64 ? (int)((const long long*)ty)[i] : ((const int*)ty)[i];
    return t & 7;
}

// ---------------- counting sort (stable compaction per type bin) ----------------
__global__ void compact_kernel(const void* __restrict__ ty1, const void* __restrict__ ty2) {
    __shared__ int sTy[N1];
    __shared__ int sBase;
    const int which = blockIdx.x >> 3;
    const int t     = blockIdx.x & 7;
    const void* ty = which ? ty2 : ty1;
    int* perm      = which ? g_perm2 : g_perm1;
    const int n = which ? N2 : N1;
    const int tid = threadIdx.x;
    const int is64 = g_is64;

    if (tid == 0) sBase = 0;
    __syncthreads();
    for (int i = tid; i < n; i += blockDim.x) sTy[i] = load_type(ty, i, is64);
    __syncthreads();
    int lc = 0;
    for (int i = tid; i < n; i += blockDim.x) lc += (sTy[i] < t) ? 1 : 0;
#pragma unroll
    for (int o = 16; o > 0; o >>= 1) lc += __shfl_down_sync(0xffffffffu, lc, o);
    if ((tid & 31) == 0) atomicAdd(&sBase, lc);
    __syncthreads();
    if (tid < 32) {
        int off = sBase;
        for (int base = 0; base < n; base += 32) {
            int i = base + tid;
            int e = (sTy[i] == t) ? 1 : 0;
            unsigned m = __ballot_sync(0xffffffffu, e != 0);
            if (e) perm[off + __popc(m & ((1u << tid) - 1u))] = i;
            off += __popc(m);
        }
        if (tid == 0) {
            if (which) { g_start2[t] = sBase; g_cnt2[t] = off - sBase; }
            else       { g_start1[t] = sBase; g_cnt1[t] = off - sBase; }
        }
    }
}

__global__ void plan_kernel() {
    int tp = 0;
    for (int t = 0; t < NTY; t++) {
        g_tilePrefix[t] = tp;
        tp += ((g_cnt1[t] + 127) >> 7) * ((g_cnt2[t] + 255) >> 8);   // 128x256 tiles
    }
    g_tilePrefix[NTY] = tp;
    g_totalTiles = tp;
}

// ---------------- convert: fp32 -> bf16 hi/lo expanded operands -----------------
__global__ void convert_kernel(const float* __restrict__ ft1, const float* __restrict__ ft2,
                               const void* __restrict__ ty1, const void* __restrict__ ty2) {
    const int pos   = blockIdx.x & (N1 - 1);
    const int which = blockIdx.x >> 13;
    const float* ft = which ? ft2 : ft1;
    const void* ty  = which ? ty2 : ty1;
    const int* perm = which ? g_perm2 : g_perm1;
    __nv_bfloat16* ftp = which ? g_ft2p : g_ft1p;
    __nv_bfloat16* slx = which ? g_sl2x : g_sl1x;
    const int tid  = threadIdx.x;                // 128 threads x 8 k each
    const int orig = perm[pos];
    const int t    = load_type(ty, orig, g_is64);

    const float4* s = (const float4*)(ft + (size_t)orig * D) + tid * 2;
    float4 a = s[0], b = s[1];
    float x[8] = {a.x, a.y, a.z, a.w, b.x, b.y, b.z, b.w};

    unsigned hi[8], lo[8];
#pragma unroll
    for (int i = 0; i < 8; i++) {
        __nv_bfloat16 h = __float2bfloat16(x[i]);
        __nv_bfloat16 l = __float2bfloat16(x[i] - __bfloat162float(h));
        hi[i] = __bfloat16_as_ushort(h);
        lo[i] = __bfloat16_as_ushort(l);
    }

    unsigned u[12];
#pragma unroll
    for (int p = 0; p < 4; p++) {
        unsigned he = hi[2 * p], ho = hi[2 * p + 1], le = lo[2 * p], lu = lo[2 * p + 1];
        if (which == 0) {   // (hi,hi,lo) per k
            u[3 * p + 0] = he | (he << 16);
            u[3 * p + 1] = le | (ho << 16);
            u[3 * p + 2] = ho | (lu << 16);
        } else {            // (hi,lo,hi) per k
            u[3 * p + 0] = he | (le << 16);
            u[3 * p + 1] = he | (ho << 16);
            u[3 * p + 2] = lu | (ho << 16);
        }
    }
    uint4 w0 = make_uint4(u[0], u[1], u[2], u[3]);
    uint4 w1 = make_uint4(u[4], u[5], u[6], u[7]);
    uint4 w2 = make_uint4(u[8], u[9], u[10], u[11]);

    uint4* df = (uint4*)((char*)ftp + (size_t)pos * (KE3 * 2) + tid * 48);
    df[0] = w0; df[1] = w1; df[2] = w2;

    if (tid >= t * 16 && tid < t * 16 + 16) {
        uint4* ds = (uint4*)((char*)slx + (size_t)orig * (KC3 * 2) + (tid - t * 16) * 48);
        ds[0] = w0; ds[1] = w1; ds[2] = w2;
    }
}

// ---------------- GEMM building blocks -------------------------------------------
// stage one chunk: A 128 rows x 128B, B 256 rows x 128B (swizzled)
__device__ __forceinline__ void issue_chunk(uint32_t stA, uint32_t stB,
        const char* gA, const char* gB, long strA, long strB,
        long rowA0, long rowB0, long maxA, long maxB, int kOff, int tid) {
    {   // A: thread -> row tid>>1, quads (tid&1)*4 .. +3
        int row = tid >> 1;
        int q0  = (tid & 1) << 2;
        long ra = rowA0 + row; if (ra > maxA) ra = maxA;
        const char* pa = gA + ra * strA + kOff;
#pragma unroll
        for (int i = 0; i < 4; i++) {
            int q = q0 + i;
            cp16(swz(stA, row, q), pa + q * 16);
        }
    }
    {   // B: thread -> row tid, quads 0..7
        int row = tid;
        long rb = rowB0 + row; if (rb > maxB) rb = maxB;
        const char* pb = gB + rb * strB + kOff;
#pragma unroll
        for (int q = 0; q < 8; q++)
            cp16(swz(stB, row, q), pb + q * 16);
    }
}

// one 128x256x64 chunk of MMAs for this warp (warp tile 64x64)
__device__ __forceinline__ void mma_chunk(float acc[4][8][4], uint32_t stA, uint32_t stB,
                                          int wm, int wn, int lane) {
#pragma unroll
    for (int j = 0; j < 4; j++) {            // k16 steps within chunk
        uint32_t a[4][4];
#pragma unroll
        for (int mi = 0; mi < 4; mi++) {
            int row  = wm * 64 + mi * 16 + (lane & 15);
            int quad = 2 * j + (lane >> 4);
            ldsm4(a[mi], swz(stA, row, quad));
        }
        uint32_t b[4][4];
#pragma unroll
        for (int np = 0; np < 4; np++) {
            int row  = wn * 64 + np * 16 + (lane & 7) + ((lane & 16) >> 1);
            int quad = 2 * j + ((lane >> 3) & 1);
            ldsm4(b[np], swz(stB, row, quad));
        }
#pragma unroll
        for (int mi = 0; mi < 4; mi++)
#pragma unroll
            for (int ni = 0; ni < 8; ni++)
                mma16816(acc[mi][ni], a[mi], b[ni >> 1][(ni & 1) * 2],
                         b[ni >> 1][(ni & 1) * 2 + 1]);
    }
}

// ---------------- cross GEMM: out = sl1x @ sl2x^T (all pairs), K=384 -------------
__global__ __launch_bounds__(256)
void cross_mma(float* __restrict__ out) {
    extern __shared__ char smc[];
    uint32_t sb = smem_u32(smc);
    const int tid = threadIdx.x, lane = tid & 31, warp = tid >> 5;
    const int wm = warp & 1, wn = warp >> 1;
    const int bi = blockIdx.y, bj = blockIdx.x;
    const char* gA = (const char*)g_sl1x;
    const char* gB = (const char*)g_sl2x;
    const long strA = KC3 * 2, strB = KC3 * 2;
    const long rA0 = (long)bi * 128, rB0 = (long)bj * 256;
    const int NC = KC3 / CHUNK_K;   // 6

    float acc[4][8][4];
#pragma unroll
    for (int mi = 0; mi < 4; mi++)
#pragma unroll
        for (int ni = 0; ni < 8; ni++)
#pragma unroll
            for (int q = 0; q < 4; q++) acc[mi][ni][q] = 0.f;

    issue_chunk(sb, sb + A_STAGE, gA, gB, strA, strB, rA0, rB0, N1 - 1, N2 - 1, 0, tid);
    CP_COMMIT();
    issue_chunk(sb + STAGE_BYTES, sb + STAGE_BYTES + A_STAGE, gA, gB, strA, strB,
                rA0, rB0, N1 - 1, N2 - 1, 128, tid);
    CP_COMMIT();

#pragma unroll 1
    for (int c = 0; c < NC; c++) {
        CP_WAIT1();
        __syncthreads();
        int cn = c + 2;
        if (cn < NC) {
            int s = cn % STAGES;
            issue_chunk(sb + s * STAGE_BYTES, sb + s * STAGE_BYTES + A_STAGE,
                        gA, gB, strA, strB, rA0, rB0, N1 - 1, N2 - 1, cn * 128, tid);
        }
        CP_COMMIT();
        int s = c % STAGES;
        mma_chunk(acc, sb + s * STAGE_BYTES, sb + s * STAGE_BYTES + A_STAGE, wm, wn, lane);
    }

    const int rbase = bi * 128 + wm * 64;
    const int cbase = bj * 256 + wn * 64;
#pragma unroll
    for (int mi = 0; mi < 4; mi++)
#pragma unroll
        for (int ni = 0; ni < 8; ni++) {
            int rr = rbase + mi * 16 + (lane >> 2);
            int cc = cbase + ni * 8 + ((lane & 3) << 1);
            *(float2*)(out + (size_t)rr * N2 + cc) =
                make_float2(acc[mi][ni][0], acc[mi][ni][1]);
            *(float2*)(out + (size_t)(rr + 8) * N2 + cc) =
                make_float2(acc[mi][ni][2], acc[mi][ni][3]);
        }
}

// ---------------- same-type GEMM: full K=3072, permuted rows, scatter ------------
__global__ __launch_bounds__(256)
void same_mma(float* __restrict__ out) {
    extern __shared__ char sms[];
    uint32_t sb = smem_u32(sms);
    const int tid = threadIdx.x, lane = tid & 31, warp = tid >> 5;
    const int wm = warp & 1, wn = warp >> 1;
    const char* gA = (const char*)g_ft1p;
    const char* gB = (const char*)g_ft2p;
    const long strA = KE3 * 2, strB = KE3 * 2;
    const int NC = KE3 / CHUNK_K;   // 48
    const int total = g_totalTiles;

#pragma unroll 1
    for (int tile = blockIdx.x; tile < total; tile += gridDim.x) {
        int t = 0;
        while (tile >= g_tilePrefix[t + 1]) t++;
        const int local = tile - g_tilePrefix[t];
        const int m = g_cnt1[t], n = g_cnt2[t];
        const int gn = (n + 255) >> 8;
        const int mbase = (local / gn) * 128, nbase = (local % gn) * 256;
        const int s1 = g_start1[t], s2 = g_start2[t];
        const long rA0 = s1 + mbase, rB0 = s2 + nbase;

        float acc[4][8][4];
#pragma unroll
        for (int mi = 0; mi < 4; mi++)
#pragma unroll
            for (int ni = 0; ni < 8; ni++)
#pragma unroll
                for (int q = 0; q < 4; q++) acc[mi][ni][q] = 0.f;

        issue_chunk(sb, sb + A_STAGE, gA, gB, strA, strB, rA0, rB0, N1 - 1, N2 - 1, 0, tid);
        CP_COMMIT();
        issue_chunk(sb + STAGE_BYTES, sb + STAGE_BYTES + A_STAGE, gA, gB, strA, strB,
                    rA0, rB0, N1 - 1, N2 - 1, 128, tid);
        CP_COMMIT();

#pragma unroll 1
        for (int c = 0; c < NC; c++) {
            CP_WAIT1();
            __syncthreads();
            int cn = c + 2;
            if (cn < NC) {
                int s = cn % STAGES;
                issue_chunk(sb + s * STAGE_BYTES, sb + s * STAGE_BYTES + A_STAGE,
                            gA, gB, strA, strB, rA0, rB0, N1 - 1, N2 - 1, cn * 128, tid);
            }
            CP_COMMIT();
            int s = c % STAGES;
            mma_chunk(acc, sb + s * STAGE_BYTES, sb + s * STAGE_BYTES + A_STAGE, wm, wn, lane);
        }

        // scattered epilogue via perm lookups (bounds-masked)
        int prow[8];
#pragma unroll
        for (int mi = 0; mi < 4; mi++) {
            int pm0 = mbase + wm * 64 + mi * 16 + (lane >> 2);
            prow[2 * mi]     = (pm0 < m)     ? g_perm1[s1 + pm0]     : -1;
            prow[2 * mi + 1] = (pm0 + 8 < m) ? g_perm1[s1 + pm0 + 8] : -1;
        }
        int pcol[16];
#pragma unroll
        for (int ni = 0; ni < 8; ni++) {
            int cn0 = nbase + wn * 64 + ni * 8 + ((lane & 3) << 1);
            pcol[2 * ni]     = (cn0 < n)     ? g_perm2[s2 + cn0]     : -1;
            pcol[2 * ni + 1] = (cn0 + 1 < n) ? g_perm2[s2 + cn0 + 1] : -1;
        }
#pragma unroll
        for (int mi = 0; mi < 4; mi++)
#pragma unroll
            for (int ni = 0; ni < 8; ni++) {
                int r0 = prow[2 * mi], r1 = prow[2 * mi + 1];
                if (r0 >= 0) {
                    float* o = out + (size_t)r0 * N2;
                    if (pcol[2 * ni] >= 0)     o[pcol[2 * ni]]     = acc[mi][ni][0];
                    if (pcol[2 * ni + 1] >= 0) o[pcol[2 * ni + 1]] = acc[mi][ni][1];
                }
                if (r1 >= 0) {
                    float* o = out + (size_t)r1 * N2;
                    if (pcol[2 * ni] >= 0)     o[pcol[2 * ni]]     = acc[mi][ni][2];
                    if (pcol[2 * ni + 1] >= 0) o[pcol[2 * ni + 1]] = acc[mi][ni][3];
                }
            }
        __syncthreads();   // smem stages reused by next tile's prologue
    }
}

// -------------------------------- launch ------------------------------------------
extern "C" void kernel_launch(void* const* d_in, const int* in_sizes, int n_in,
                              void* d_out, int out_size) {
    const float* ft1 = (const float*)d_in[0];
    const float* ft2 = (const float*)d_in[1];
    const void*  ty1 = d_in[2];
    const void*  ty2 = d_in[3];
    float* out = (float*)d_out;

    cudaFuncSetAttribute(cross_mma, cudaFuncAttributeMaxDynamicSharedMemorySize, SMEM_BYTES);
    cudaFuncSetAttribute(same_mma,  cudaFuncAttributeMaxDynamicSharedMemorySize, SMEM_BYTES);

    detect_kernel<<<1, 256>>>((const int*)ty1);
    compact_kernel<<<16, 256>>>(ty1, ty2);
    plan_kernel<<<1, 1>>>();
    convert_kernel<<<2 * N1, 128>>>(ft1, ft2, ty1, ty2);

    dim3 gc(N2 / 256, N1 / 128);                   // 32 x 64
    cross_mma<<<gc, 256, SMEM_BYTES>>>(out);       // writes every element (cross value)
    same_mma<<<512, 256, SMEM_BYTES>>>(out);       // overwrites same-type pairs (full dot)
}

// round 13
// speedup vs baseline: 1.1237x; 1.1237x over previous
#include <cuda_runtime.h>
#include <cuda_bf16.h>
#include <stdint.h>

#define N1 8192
#define N2 8192
#define D  1024
#define C  128
#define NTY 8
#define KE3 3072            // 3*D  expanded K (same-type GEMM)
#define KC3 384             // 3*C  expanded K (cross GEMM)

#define STAGES      3
#define CHUNK_K     64                        // bf16 k per chunk
#define STAGE_HALF  (128 * 128)               // 128 rows x 128B = 16 KB
#define STAGE_BYTES (2 * STAGE_HALF)          // A + B = 32 KB
#define SMEM_BYTES  (STAGES * STAGE_BYTES)    // 96 KB -> 2 CTAs/SM

// ---------------- device scratch (static: no runtime allocation) ----------------
__device__ __align__(1024) __nv_bfloat16 g_ft1p[(size_t)N1 * KE3];  // perm order, (hi,hi,lo)
__device__ __align__(1024) __nv_bfloat16 g_ft2p[(size_t)N2 * KE3];  // perm order, (hi,lo,hi)
__device__ __align__(1024) __nv_bfloat16 g_sl1x[(size_t)N1 * KC3];  // orig order, (hi,hi,lo)
__device__ __align__(1024) __nv_bfloat16 g_sl2x[(size_t)N2 * KC3];  // orig order, (hi,lo,hi)
__device__ int g_perm1[N1], g_perm2[N2];
__device__ int g_start1[NTY], g_cnt1[NTY];
__device__ int g_start2[NTY], g_cnt2[NTY];
__device__ int g_tilePrefix[NTY + 1];
__device__ int g_totalTiles;
__device__ int g_is64;

// ---------------- small PTX helpers (base ISA, compute_103-safe) ----------------
__device__ __forceinline__ uint32_t smem_u32(const void* p) {
    uint32_t a;
    asm("{ .reg .u64 t; cvta.to.shared.u64 t, %1; cvt.u32.u64 %0, t; }" : "=r"(a) : "l"(p));
    return a;
}
__device__ __forceinline__ void cp16(uint32_t s, const void* g) {
    asm volatile("cp.async.cg.shared.global [%0], [%1], 16;" :: "r"(s), "l"(g));
}
#define CP_COMMIT() asm volatile("cp.async.commit_group;" ::: "memory")
#define CP_WAIT1()  asm volatile("cp.async.wait_group 1;" ::: "memory")

__device__ __forceinline__ void ldsm4(uint32_t r[4], uint32_t addr) {
    asm volatile("ldmatrix.sync.aligned.m8n8.x4.shared.b16 {%0,%1,%2,%3}, [%4];"
                 : "=r"(r[0]), "=r"(r[1]), "=r"(r[2]), "=r"(r[3]) : "r"(addr));
}
__device__ __forceinline__ void mma16816(float c[4], const uint32_t a[4],
                                         uint32_t b0, uint32_t b1) {
    asm volatile("mma.sync.aligned.m16n8k16.row.col.f32.bf16.bf16.f32 "
                 "{%0,%1,%2,%3}, {%4,%5,%6,%7}, {%8,%9}, {%0,%1,%2,%3};"
                 : "+f"(c[0]), "+f"(c[1]), "+f"(c[2]), "+f"(c[3])
                 : "r"(a[0]), "r"(a[1]), "r"(a[2]), "r"(a[3]), "r"(b0), "r"(b1));
}
// swizzled smem address: rows 128B, 16B quads, quad' = quad ^ (row & 7)
__device__ __forceinline__ uint32_t swz(uint32_t base, int row, int quad) {
    return base + row * 128 + ((quad ^ (row & 7)) << 4);
}

// ---------------- dtype detection (int64 vs silently-downgraded int32) ----------
__global__ void detect_kernel(const int* __restrict__ tyraw) {
    __shared__ int sAny;
    if (threadIdx.x == 0) sAny = 0;
    __syncthreads();
    int any = 0;
    for (int i = threadIdx.x; i < 4096; i += blockDim.x) any |= (tyraw[2 * i + 1] != 0);
    if (any) atomicOr(&sAny, 1);
    __syncthreads();
    if (threadIdx.x == 0) g_is64 = sAny ? 0 : 1;
}
__device__ __forceinline__ int load_type(const void* ty, int i, int is64) {
    int t = is64 ? (int)((const long long*)ty)[i] : ((const int*)ty)[i];
    return t & 7;
}

// ---------------- counting sort (stable compaction per type bin) ----------------
__global__ void compact_kernel(const void* __restrict__ ty1, const void* __restrict__ ty2) {
    __shared__ int sTy[N1];
    __shared__ int sBase;
    const int which = blockIdx.x >> 3;
    const int t     = blockIdx.x & 7;
    const void* ty = which ? ty2 : ty1;
    int* perm      = which ? g_perm2 : g_perm1;
    const int n = which ? N2 : N1;
    const int tid = threadIdx.x;
    const int is64 = g_is64;

    if (tid == 0) sBase = 0;
    __syncthreads();
    for (int i = tid; i < n; i += blockDim.x) sTy[i] = load_type(ty, i, is64);
    __syncthreads();
    int lc = 0;
    for (int i = tid; i < n; i += blockDim.x) lc += (sTy[i] < t) ? 1 : 0;
#pragma unroll
    for (int o = 16; o > 0; o >>= 1) lc += __shfl_down_sync(0xffffffffu, lc, o);
    if ((tid & 31) == 0) atomicAdd(&sBase, lc);
    __syncthreads();
    if (tid < 32) {
        int off = sBase;
        for (int base = 0; base < n; base += 32) {
            int i = base + tid;
            int e = (sTy[i] == t) ? 1 : 0;
            unsigned m = __ballot_sync(0xffffffffu, e != 0);
            if (e) perm[off + __popc(m & ((1u << tid) - 1u))] = i;
            off += __popc(m);
        }
        if (tid == 0) {
            if (which) { g_start2[t] = sBase; g_cnt2[t] = off - sBase; }
            else       { g_start1[t] = sBase; g_cnt1[t] = off - sBase; }
        }
    }
}

__global__ void plan_kernel() {
    int tp = 0;
    for (int t = 0; t < NTY; t++) {
        g_tilePrefix[t] = tp;
        tp += ((g_cnt1[t] + 127) >> 7) * ((g_cnt2[t] + 127) >> 7);   // 128x128 tiles
    }
    g_tilePrefix[NTY] = tp;
    g_totalTiles = tp;
}

// ---------------- convert: fp32 -> bf16 hi/lo expanded operands -----------------
__global__ void convert_kernel(const float* __restrict__ ft1, const float* __restrict__ ft2,
                               const void* __restrict__ ty1, const void* __restrict__ ty2) {
    const int pos   = blockIdx.x & (N1 - 1);
    const int which = blockIdx.x >> 13;
    const float* ft = which ? ft2 : ft1;
    const void* ty  = which ? ty2 : ty1;
    const int* perm = which ? g_perm2 : g_perm1;
    __nv_bfloat16* ftp = which ? g_ft2p : g_ft1p;
    __nv_bfloat16* slx = which ? g_sl2x : g_sl1x;
    const int tid  = threadIdx.x;                // 128 threads x 8 k each
    const int orig = perm[pos];
    const int t    = load_type(ty, orig, g_is64);

    const float4* s = (const float4*)(ft + (size_t)orig * D) + tid * 2;
    float4 a = s[0], b = s[1];
    float x[8] = {a.x, a.y, a.z, a.w, b.x, b.y, b.z, b.w};

    unsigned hi[8], lo[8];
#pragma unroll
    for (int i = 0; i < 8; i++) {
        __nv_bfloat16 h = __float2bfloat16(x[i]);
        __nv_bfloat16 l = __float2bfloat16(x[i] - __bfloat162float(h));
        hi[i] = __bfloat16_as_ushort(h);
        lo[i] = __bfloat16_as_ushort(l);
    }

    unsigned u[12];
#pragma unroll
    for (int p = 0; p < 4; p++) {
        unsigned he = hi[2 * p], ho = hi[2 * p + 1], le = lo[2 * p], lu = lo[2 * p + 1];
        if (which == 0) {   // (hi,hi,lo) per k
            u[3 * p + 0] = he | (he << 16);
            u[3 * p + 1] = le | (ho << 16);
            u[3 * p + 2] = ho | (lu << 16);
        } else {            // (hi,lo,hi) per k
            u[3 * p + 0] = he | (le << 16);
            u[3 * p + 1] = he | (ho << 16);
            u[3 * p + 2] = lu | (ho << 16);
        }
    }
    uint4 w0 = make_uint4(u[0], u[1], u[2], u[3]);
    uint4 w1 = make_uint4(u[4], u[5], u[6], u[7]);
    uint4 w2 = make_uint4(u[8], u[9], u[10], u[11]);

    uint4* df = (uint4*)((char*)ftp + (size_t)pos * (KE3 * 2) + tid * 48);
    df[0] = w0; df[1] = w1; df[2] = w2;

    if (tid >= t * 16 && tid < t * 16 + 16) {
        uint4* ds = (uint4*)((char*)slx + (size_t)orig * (KC3 * 2) + (tid - t * 16) * 48);
        ds[0] = w0; ds[1] = w1; ds[2] = w2;
    }
}

// ---------------- GEMM building blocks -------------------------------------------
// stage one chunk with 128 threads: A row tid (8 quads), B row tid (8 quads)
__device__ __forceinline__ void issue_chunk(uint32_t stA, uint32_t stB,
        const char* gA, const char* gB, long strA, long strB,
        long rowA0, long rowB0, long maxA, long maxB, int kOff, int tid) {
    int row = tid;
    long ra = rowA0 + row; if (ra > maxA) ra = maxA;
    long rb = rowB0 + row; if (rb > maxB) rb = maxB;
    const char* pa = gA + ra * strA + kOff;
    const char* pb = gB + rb * strB + kOff;
#pragma unroll
    for (int q = 0; q < 8; q++) {
        cp16(swz(stA, row, q), pa + q * 16);
        cp16(swz(stB, row, q), pb + q * 16);
    }
}

// one 128x128x64 chunk of MMAs for this warp (warp tile 64x64, 4 warps 2x2)
__device__ __forceinline__ void mma_chunk(float acc[4][8][4], uint32_t stA, uint32_t stB,
                                          int wm, int wn, int lane) {
#pragma unroll
    for (int j = 0; j < 4; j++) {            // k16 steps within chunk
        uint32_t a[4][4];
#pragma unroll
        for (int mi = 0; mi < 4; mi++) {
            int row  = wm * 64 + mi * 16 + (lane & 15);
            int quad = 2 * j + (lane >> 4);
            ldsm4(a[mi], swz(stA, row, quad));
        }
        uint32_t b[4][4];
#pragma unroll
        for (int np = 0; np < 4; np++) {
            int row  = wn * 64 + np * 16 + (lane & 7) + ((lane & 16) >> 1);
            int quad = 2 * j + ((lane >> 3) & 1);
            ldsm4(b[np], swz(stB, row, quad));
        }
#pragma unroll
        for (int mi = 0; mi < 4; mi++)
#pragma unroll
            for (int ni = 0; ni < 8; ni++)
                mma16816(acc[mi][ni], a[mi], b[ni >> 1][(ni & 1) * 2],
                         b[ni >> 1][(ni & 1) * 2 + 1]);
    }
}

// ---------------- cross GEMM: out = sl1x @ sl2x^T (all pairs), K=384 -------------
__global__ __launch_bounds__(128, 2)
void cross_mma(float* __restrict__ out) {
    extern __shared__ char smc[];
    uint32_t sb = smem_u32(smc);
    const int tid = threadIdx.x, lane = tid & 31, warp = tid >> 5;
    const int wm = warp & 1, wn = warp >> 1;          // 2x2 warps
    const int bi = blockIdx.y, bj = blockIdx.x;
    const char* gA = (const char*)g_sl1x;
    const char* gB = (const char*)g_sl2x;
    const long strA = KC3 * 2, strB = KC3 * 2;
    const long rA0 = (long)bi * 128, rB0 = (long)bj * 128;
    const int NC = KC3 / CHUNK_K;   // 6

    float acc[4][8][4];
#pragma unroll
    for (int mi = 0; mi < 4; mi++)
#pragma unroll
        for (int ni = 0; ni < 8; ni++)
#pragma unroll
            for (int q = 0; q < 4; q++) acc[mi][ni][q] = 0.f;

    issue_chunk(sb, sb + STAGE_HALF, gA, gB, strA, strB, rA0, rB0, N1 - 1, N2 - 1, 0, tid);
    CP_COMMIT();
    issue_chunk(sb + STAGE_BYTES, sb + STAGE_BYTES + STAGE_HALF, gA, gB, strA, strB,
                rA0, rB0, N1 - 1, N2 - 1, 128, tid);
    CP_COMMIT();

#pragma unroll 1
    for (int c = 0; c < NC; c++) {
        CP_WAIT1();
        __syncthreads();
        int cn = c + 2;
        if (cn < NC) {
            int s = cn % STAGES;
            issue_chunk(sb + s * STAGE_BYTES, sb + s * STAGE_BYTES + STAGE_HALF,
                        gA, gB, strA, strB, rA0, rB0, N1 - 1, N2 - 1, cn * 128, tid);
        }
        CP_COMMIT();
        int s = c % STAGES;
        mma_chunk(acc, sb + s * STAGE_BYTES, sb + s * STAGE_BYTES + STAGE_HALF, wm, wn, lane);
    }

    const int rbase = bi * 128 + wm * 64;
    const int cbase = bj * 128 + wn * 64;
#pragma unroll
    for (int mi = 0; mi < 4; mi++)
#pragma unroll
        for (int ni = 0; ni < 8; ni++) {
            int rr = rbase + mi * 16 + (lane >> 2);
            int cc = cbase + ni * 8 + ((lane & 3) << 1);
            *(float2*)(out + (size_t)rr * N2 + cc) =
                make_float2(acc[mi][ni][0], acc[mi][ni][1]);
            *(float2*)(out + (size_t)(rr + 8) * N2 + cc) =
                make_float2(acc[mi][ni][2], acc[mi][ni][3]);
        }
}

// ---------------- same-type GEMM: full K=3072, permuted rows, scatter ------------
__global__ __launch_bounds__(128, 2)
void same_mma(float* __restrict__ out) {
    extern __shared__ char sms[];
    uint32_t sb = smem_u32(sms);
    const int tid = threadIdx.x, lane = tid & 31, warp = tid >> 5;
    const int wm = warp & 1, wn = warp >> 1;
    const char* gA = (const char*)g_ft1p;
    const char* gB = (const char*)g_ft2p;
    const long strA = KE3 * 2, strB = KE3 * 2;
    const int NC = KE3 / CHUNK_K;   // 48
    const int total = g_totalTiles;

#pragma unroll 1
    for (int tile = blockIdx.x; tile < total; tile += gridDim.x) {
        int t = 0;
        while (tile >= g_tilePrefix[t + 1]) t++;
        const int local = tile - g_tilePrefix[t];
        const int m = g_cnt1[t], n = g_cnt2[t];
        const int gn = (n + 127) >> 7;
        const int mbase = (local / gn) * 128, nbase = (local % gn) * 128;
        const int s1 = g_start1[t], s2 = g_start2[t];
        const long rA0 = s1 + mbase, rB0 = s2 + nbase;

        float acc[4][8][4];
#pragma unroll
        for (int mi = 0; mi < 4; mi++)
#pragma unroll
            for (int ni = 0; ni < 8; ni++)
#pragma unroll
                for (int q = 0; q < 4; q++) acc[mi][ni][q] = 0.f;

        issue_chunk(sb, sb + STAGE_HALF, gA, gB, strA, strB, rA0, rB0, N1 - 1, N2 - 1, 0, tid);
        CP_COMMIT();
        issue_chunk(sb + STAGE_BYTES, sb + STAGE_BYTES + STAGE_HALF, gA, gB, strA, strB,
                    rA0, rB0, N1 - 1, N2 - 1, 128, tid);
        CP_COMMIT();

#pragma unroll 1
        for (int c = 0; c < NC; c++) {
            CP_WAIT1();
            __syncthreads();
            int cn = c + 2;
            if (cn < NC) {
                int s = cn % STAGES;
                issue_chunk(sb + s * STAGE_BYTES, sb + s * STAGE_BYTES + STAGE_HALF,
                            gA, gB, strA, strB, rA0, rB0, N1 - 1, N2 - 1, cn * 128, tid);
            }
            CP_COMMIT();
            int s = c % STAGES;
            mma_chunk(acc, sb + s * STAGE_BYTES, sb + s * STAGE_BYTES + STAGE_HALF, wm, wn, lane);
        }

        // scattered epilogue via perm lookups (bounds-masked)
        int prow[8];
#pragma unroll
        for (int mi = 0; mi < 4; mi++) {
            int pm0 = mbase + wm * 64 + mi * 16 + (lane >> 2);
            prow[2 * mi]     = (pm0 < m)     ? g_perm1[s1 + pm0]     : -1;
            prow[2 * mi + 1] = (pm0 + 8 < m) ? g_perm1[s1 + pm0 + 8] : -1;
        }
        int pcol[16];
#pragma unroll
        for (int ni = 0; ni < 8; ni++) {
            int cn0 = nbase + wn * 64 + ni * 8 + ((lane & 3) << 1);
            pcol[2 * ni]     = (cn0 < n)     ? g_perm2[s2 + cn0]     : -1;
            pcol[2 * ni + 1] = (cn0 + 1 < n) ? g_perm2[s2 + cn0 + 1] : -1;
        }
#pragma unroll
        for (int mi = 0; mi < 4; mi++)
#pragma unroll
            for (int ni = 0; ni < 8; ni++) {
                int r0 = prow[2 * mi], r1 = prow[2 * mi + 1];
                if (r0 >= 0) {
                    float* o = out + (size_t)r0 * N2;
                    if (pcol[2 * ni] >= 0)     o[pcol[2 * ni]]     = acc[mi][ni][0];
                    if (pcol[2 * ni + 1] >= 0) o[pcol[2 * ni + 1]] = acc[mi][ni][1];
                }
                if (r1 >= 0) {
                    float* o = out + (size_t)r1 * N2;
                    if (pcol[2 * ni] >= 0)     o[pcol[2 * ni]]     = acc[mi][ni][2];
                    if (pcol[2 * ni + 1] >= 0) o[pcol[2 * ni + 1]] = acc[mi][ni][3];
                }
            }
        __syncthreads();   // smem stages reused by next tile's prologue
    }
}

// -------------------------------- launch ------------------------------------------
extern "C" void kernel_launch(void* const* d_in, const int* in_sizes, int n_in,
                              void* d_out, int out_size) {
    const float* ft1 = (const float*)d_in[0];
    const float* ft2 = (const float*)d_in[1];
    const void*  ty1 = d_in[2];
    const void*  ty2 = d_in[3];
    float* out = (float*)d_out;

    cudaFuncSetAttribute(cross_mma, cudaFuncAttributeMaxDynamicSharedMemorySize, SMEM_BYTES);
    cudaFuncSetAttribute(same_mma,  cudaFuncAttributeMaxDynamicSharedMemorySize, SMEM_BYTES);

    detect_kernel<<<1, 256>>>((const int*)ty1);
    compact_kernel<<<16, 256>>>(ty1, ty2);
    plan_kernel<<<1, 1>>>();
    convert_kernel<<<2 * N1, 128>>>(ft1, ft2, ty1, ty2);

    dim3 gc(N2 / 128, N1 / 128);                   // 64 x 64
    cross_mma<<<gc, 128, SMEM_BYTES>>>(out);       // writes every element (cross value)
    same_mma<<<592, 128, SMEM_BYTES>>>(out);       // overwrites same-type pairs (full dot)
}

// round 14
// speedup vs baseline: 1.9583x; 1.7428x over previous
#include <cuda_runtime.h>
#include <cuda_fp16.h>
#include <stdint.h>

#define N1 8192
#define N2 8192
#define D  1024
#define C  128
#define NTY 8
#define KE2 2048            // 2*D  expanded K (same-type GEMM)
#define KC2 256             // 2*C  expanded K (cross GEMM)

#define STAGES      3
#define CHUNK_K     64                       // fp16 k per chunk
#define STAGE_HALF  (128 * 128)              // 128 rows x 128B  = 16 KB
#define STAGE_BYTES (2 * STAGE_HALF)         // A + B            = 32 KB
#define SMEM_BYTES  (STAGES * STAGE_BYTES)   // 96 KB -> 2 CTAs/SM

// ---------------- device scratch (static: no runtime allocation) ----------------
__device__ __align__(1024) __half g_ft1p[(size_t)N1 * KE2];  // perm order, (hi,lo)
__device__ __align__(1024) __half g_ft2p[(size_t)N2 * KE2];  // perm order, (hi,hi)
__device__ __align__(1024) __half g_sl1x[(size_t)N1 * KC2];  // orig order, (hi,lo)
__device__ __align__(1024) __half g_sl2x[(size_t)N2 * KC2];  // orig order, (hi,hi)
__device__ int g_perm1[N1], g_perm2[N2];
__device__ int g_start1[NTY], g_cnt1[NTY];
__device__ int g_start2[NTY], g_cnt2[NTY];
__device__ int g_tilePrefix[NTY + 1];
__device__ int g_totalTiles;
__device__ int g_is64;

// ---------------- small PTX helpers (base ISA, compute_103-safe) ----------------
__device__ __forceinline__ uint32_t smem_u32(const void* p) {
    uint32_t a;
    asm("{ .reg .u64 t; cvta.to.shared.u64 t, %1; cvt.u32.u64 %0, t; }" : "=r"(a) : "l"(p));
    return a;
}
__device__ __forceinline__ void cp16(uint32_t s, const void* g) {
    asm volatile("cp.async.cg.shared.global [%0], [%1], 16;" :: "r"(s), "l"(g));
}
#define CP_COMMIT() asm volatile("cp.async.commit_group;" ::: "memory")
#define CP_WAIT1()  asm volatile("cp.async.wait_group 1;" ::: "memory")

__device__ __forceinline__ void ldsm4(uint32_t r[4], uint32_t addr) {
    asm volatile("ldmatrix.sync.aligned.m8n8.x4.shared.b16 {%0,%1,%2,%3}, [%4];"
                 : "=r"(r[0]), "=r"(r[1]), "=r"(r[2]), "=r"(r[3]) : "r"(addr));
}
__device__ __forceinline__ void mma16816(float c[4], const uint32_t a[4],
                                         uint32_t b0, uint32_t b1) {
    asm volatile("mma.sync.aligned.m16n8k16.row.col.f32.f16.f16.f32 "
                 "{%0,%1,%2,%3}, {%4,%5,%6,%7}, {%8,%9}, {%0,%1,%2,%3};"
                 : "+f"(c[0]), "+f"(c[1]), "+f"(c[2]), "+f"(c[3])
                 : "r"(a[0]), "r"(a[1]), "r"(a[2]), "r"(a[3]), "r"(b0), "r"(b1));
}
// swizzled smem address: rows 128B, 16B quads, quad' = quad ^ (row & 7)
__device__ __forceinline__ uint32_t swz(uint32_t base, int row, int quad) {
    return base + row * 128 + ((quad ^ (row & 7)) << 4);
}

// ---------------- dtype detection (int64 vs silently-downgraded int32) ----------
__global__ void detect_kernel(const int* __restrict__ tyraw) {
    __shared__ int sAny;
    if (threadIdx.x == 0) sAny = 0;
    __syncthreads();
    int any = 0;
    for (int i = threadIdx.x; i < 4096; i += blockDim.x) any |= (tyraw[2 * i + 1] != 0);
    if (any) atomicOr(&sAny, 1);
    __syncthreads();
    if (threadIdx.x == 0) g_is64 = sAny ? 0 : 1;
}
__device__ __forceinline__ int load_type(const void* ty, int i, int is64) {
    int t = is64 ? (int)((const long long*)ty)[i] : ((const int*)ty)[i];
    return t & 7;
}

// ---------------- counting sort (stable compaction per type bin) ----------------
__global__ void compact_kernel(const void* __restrict__ ty1, const void* __restrict__ ty2) {
    __shared__ int sTy[N1];
    __shared__ int sBase;
    const int which = blockIdx.x >> 3;
    const int t     = blockIdx.x & 7;
    const void* ty = which ? ty2 : ty1;
    int* perm      = which ? g_perm2 : g_perm1;
    const int n = which ? N2 : N1;
    const int tid = threadIdx.x;
    const int is64 = g_is64;

    if (tid == 0) sBase = 0;
    __syncthreads();
    for (int i = tid; i < n; i += blockDim.x) sTy[i] = load_type(ty, i, is64);
    __syncthreads();
    int lc = 0;
    for (int i = tid; i < n; i += blockDim.x) lc += (sTy[i] < t) ? 1 : 0;
#pragma unroll
    for (int o = 16; o > 0; o >>= 1) lc += __shfl_down_sync(0xffffffffu, lc, o);
    if ((tid & 31) == 0) atomicAdd(&sBase, lc);
    __syncthreads();
    if (tid < 32) {
        int off = sBase;
        for (int base = 0; base < n; base += 32) {
            int i = base + tid;
            int e = (sTy[i] == t) ? 1 : 0;
            unsigned m = __ballot_sync(0xffffffffu, e != 0);
            if (e) perm[off + __popc(m & ((1u << tid) - 1u))] = i;
            off += __popc(m);
        }
        if (tid == 0) {
            if (which) { g_start2[t] = sBase; g_cnt2[t] = off - sBase; }
            else       { g_start1[t] = sBase; g_cnt1[t] = off - sBase; }
        }
    }
}

__global__ void plan_kernel() {
    int tp = 0;
    for (int t = 0; t < NTY; t++) {
        g_tilePrefix[t] = tp;
        tp += ((g_cnt1[t] + 127) >> 7) * ((g_cnt2[t] + 127) >> 7);   // 128x128 tiles
    }
    g_tilePrefix[NTY] = tp;
    g_totalTiles = tp;
}

// ---------------- convert: fp32 -> fp16 hi/lo 2-term expanded operands ----------
// per original k: A side (hi, lo); B side (hi, hi).  Sum of slot products = a * hb,
// dropped term a*lb with |lb| <= 2^-11 |b|  -> norm rel err ~1.7e-4 << 1e-3.
__global__ void convert_kernel(const float* __restrict__ ft1, const float* __restrict__ ft2,
                               const void* __restrict__ ty1, const void* __restrict__ ty2) {
    const int pos   = blockIdx.x & (N1 - 1);
    const int which = blockIdx.x >> 13;
    const float* ft = which ? ft2 : ft1;
    const void* ty  = which ? ty2 : ty1;
    const int* perm = which ? g_perm2 : g_perm1;
    __half* ftp = which ? g_ft2p : g_ft1p;
    __half* slx = which ? g_sl2x : g_sl1x;
    const int tid  = threadIdx.x;                // 128 threads x 8 k each
    const int orig = perm[pos];
    const int t    = load_type(ty, orig, g_is64);

    const float4* s = (const float4*)(ft + (size_t)orig * D) + tid * 2;
    float4 a = s[0], b = s[1];
    float x[8] = {a.x, a.y, a.z, a.w, b.x, b.y, b.z, b.w};

    unsigned u[8];
#pragma unroll
    for (int i = 0; i < 8; i++) {
        __half h = __float2half(x[i]);
        unsigned hu = __half_as_ushort(h);
        if (which == 0) {   // A side: (hi, lo)
            __half l = __float2half(x[i] - __half2float(h));
            u[i] = hu | ((unsigned)__half_as_ushort(l) << 16);
        } else {            // B side: (hi, hi)
            u[i] = hu | (hu << 16);
        }
    }
    uint4 w0 = make_uint4(u[0], u[1], u[2], u[3]);
    uint4 w1 = make_uint4(u[4], u[5], u[6], u[7]);

    uint4* df = (uint4*)((char*)ftp + (size_t)pos * (KE2 * 2) + tid * 32);
    df[0] = w0; df[1] = w1;

    if (tid >= t * 16 && tid < t * 16 + 16) {
        uint4* ds = (uint4*)((char*)slx + (size_t)orig * (KC2 * 2) + (tid - t * 16) * 32);
        ds[0] = w0; ds[1] = w1;
    }
}

// ---------------- GEMM building blocks (R11-proven config) -----------------------
// load one 128x64-fp16 chunk of A and B into a swizzled smem stage (256 threads)
__device__ __forceinline__ void issue_chunk(uint32_t stA, uint32_t stB,
        const char* gA, const char* gB, long strA, long strB,
        long rowA0, long rowB0, long maxA, long maxB, int kOff, int tid) {
    int row = tid >> 1;
    int q0  = (tid & 1) << 2;
    long ra = rowA0 + row; if (ra > maxA) ra = maxA;
    long rb = rowB0 + row; if (rb > maxB) rb = maxB;
    const char* pa = gA + ra * strA + kOff;
    const char* pb = gB + rb * strB + kOff;
#pragma unroll
    for (int i = 0; i < 4; i++) {
        int q = q0 + i;
        cp16(swz(stA, row, q), pa + q * 16);
        cp16(swz(stB, row, q), pb + q * 16);
    }
}

// one 128x128x64 chunk of MMAs for this warp (warp tile 64x32, 8 warps 2x4)
__device__ __forceinline__ void mma_chunk(float acc[4][4][4], uint32_t stA, uint32_t stB,
                                          int wm, int wn, int lane) {
#pragma unroll
    for (int j = 0; j < 4; j++) {            // k16 steps within chunk
        uint32_t a[4][4];
#pragma unroll
        for (int mi = 0; mi < 4; mi++) {
            int row  = wm * 64 + mi * 16 + (lane & 15);
            int quad = 2 * j + (lane >> 4);
            ldsm4(a[mi], swz(stA, row, quad));
        }
        uint32_t b[2][4];
#pragma unroll
        for (int np = 0; np < 2; np++) {
            int row  = wn * 32 + np * 16 + (lane & 7) + ((lane & 16) >> 1);
            int quad = 2 * j + ((lane >> 3) & 1);
            ldsm4(b[np], swz(stB, row, quad));
        }
#pragma unroll
        for (int mi = 0; mi < 4; mi++)
#pragma unroll
            for (int ni = 0; ni < 4; ni++)
                mma16816(acc[mi][ni], a[mi], b[ni >> 1][(ni & 1) * 2],
                         b[ni >> 1][(ni & 1) * 2 + 1]);
    }
}

// ---------------- cross GEMM: out = sl1x @ sl2x^T (all pairs), K=256 -------------
__global__ __launch_bounds__(256)
void cross_mma(float* __restrict__ out) {
    extern __shared__ char smc[];
    uint32_t sb = smem_u32(smc);
    const int tid = threadIdx.x, lane = tid & 31, warp = tid >> 5;
    const int wm = warp & 1, wn = warp >> 1;
    const int bi = blockIdx.y, bj = blockIdx.x;
    const char* gA = (const char*)g_sl1x;
    const char* gB = (const char*)g_sl2x;
    const long strA = KC2 * 2, strB = KC2 * 2;
    const long rA0 = (long)bi * 128, rB0 = (long)bj * 128;
    const int NC = KC2 / CHUNK_K;   // 4

    float acc[4][4][4];
#pragma unroll
    for (int mi = 0; mi < 4; mi++)
#pragma unroll
        for (int ni = 0; ni < 4; ni++)
#pragma unroll
            for (int q = 0; q < 4; q++) acc[mi][ni][q] = 0.f;

    issue_chunk(sb, sb + STAGE_HALF, gA, gB, strA, strB, rA0, rB0, N1 - 1, N2 - 1, 0, tid);
    CP_COMMIT();
    issue_chunk(sb + STAGE_BYTES, sb + STAGE_BYTES + STAGE_HALF, gA, gB, strA, strB,
                rA0, rB0, N1 - 1, N2 - 1, 128, tid);
    CP_COMMIT();

#pragma unroll 1
    for (int c = 0; c < NC; c++) {
        CP_WAIT1();
        __syncthreads();
        int cn = c + 2;
        if (cn < NC) {
            int s = cn % STAGES;
            issue_chunk(sb + s * STAGE_BYTES, sb + s * STAGE_BYTES + STAGE_HALF,
                        gA, gB, strA, strB, rA0, rB0, N1 - 1, N2 - 1, cn * 128, tid);
        }
        CP_COMMIT();
        int s = c % STAGES;
        mma_chunk(acc, sb + s * STAGE_BYTES, sb + s * STAGE_BYTES + STAGE_HALF, wm, wn, lane);
    }

    const int rbase = bi * 128 + wm * 64;
    const int cbase = bj * 128 + wn * 32;
#pragma unroll
    for (int mi = 0; mi < 4; mi++)
#pragma unroll
        for (int ni = 0; ni < 4; ni++) {
            int rr = rbase + mi * 16 + (lane >> 2);
            int cc = cbase + ni * 8 + ((lane & 3) << 1);
            *(float2*)(out + (size_t)rr * N2 + cc) =
                make_float2(acc[mi][ni][0], acc[mi][ni][1]);
            *(float2*)(out + (size_t)(rr + 8) * N2 + cc) =
                make_float2(acc[mi][ni][2], acc[mi][ni][3]);
        }
}

// ---------------- same-type GEMM: full K=2048, permuted rows, scatter ------------
__global__ __launch_bounds__(256)
void same_mma(float* __restrict__ out) {
    extern __shared__ char sms[];
    uint32_t sb = smem_u32(sms);
    const int tid = threadIdx.x, lane = tid & 31, warp = tid >> 5;
    const int wm = warp & 1, wn = warp >> 1;
    const char* gA = (const char*)g_ft1p;
    const char* gB = (const char*)g_ft2p;
    const long strA = KE2 * 2, strB = KE2 * 2;
    const int NC = KE2 / CHUNK_K;   // 32
    const int total = g_totalTiles;

#pragma unroll 1
    for (int tile = blockIdx.x; tile < total; tile += gridDim.x) {
        int t = 0;
        while (tile >= g_tilePrefix[t + 1]) t++;
        const int local = tile - g_tilePrefix[t];
        const int m = g_cnt1[t], n = g_cnt2[t];
        const int gn = (n + 127) >> 7;
        const int mbase = (local / gn) * 128, nbase = (local % gn) * 128;
        const int s1 = g_start1[t], s2 = g_start2[t];
        const long rA0 = s1 + mbase, rB0 = s2 + nbase;

        float acc[4][4][4];
#pragma unroll
        for (int mi = 0; mi < 4; mi++)
#pragma unroll
            for (int ni = 0; ni < 4; ni++)
#pragma unroll
                for (int q = 0; q < 4; q++) acc[mi][ni][q] = 0.f;

        issue_chunk(sb, sb + STAGE_HALF, gA, gB, strA, strB, rA0, rB0, N1 - 1, N2 - 1, 0, tid);
        CP_COMMIT();
        issue_chunk(sb + STAGE_BYTES, sb + STAGE_BYTES + STAGE_HALF, gA, gB, strA, strB,
                    rA0, rB0, N1 - 1, N2 - 1, 128, tid);
        CP_COMMIT();

#pragma unroll 1
        for (int c = 0; c < NC; c++) {
            CP_WAIT1();
            __syncthreads();
            int cn = c + 2;
            if (cn < NC) {
                int s = cn % STAGES;
                issue_chunk(sb + s * STAGE_BYTES, sb + s * STAGE_BYTES + STAGE_HALF,
                            gA, gB, strA, strB, rA0, rB0, N1 - 1, N2 - 1, cn * 128, tid);
            }
            CP_COMMIT();
            int s = c % STAGES;
            mma_chunk(acc, sb + s * STAGE_BYTES, sb + s * STAGE_BYTES + STAGE_HALF, wm, wn, lane);
        }

        // scattered epilogue via perm lookups (bounds-masked)
        int prow[8];
#pragma unroll
        for (int mi = 0; mi < 4; mi++) {
            int pm0 = mbase + wm * 64 + mi * 16 + (lane >> 2);
            prow[2 * mi]     = (pm0 < m)     ? g_perm1[s1 + pm0]     : -1;
            prow[2 * mi + 1] = (pm0 + 8 < m) ? g_perm1[s1 + pm0 + 8] : -1;
        }
        int pcol[8];
#pragma unroll
        for (int ni = 0; ni < 4; ni++) {
            int cn0 = nbase + wn * 32 + ni * 8 + ((lane & 3) << 1);
            pcol[2 * ni]     = (cn0 < n)     ? g_perm2[s2 + cn0]     : -1;
            pcol[2 * ni + 1] = (cn0 + 1 < n) ? g_perm2[s2 + cn0 + 1] : -1;
        }
#pragma unroll
        for (int mi = 0; mi < 4; mi++)
#pragma unroll
            for (int ni = 0; ni < 4; ni++) {
                int r0 = prow[2 * mi], r1 = prow[2 * mi + 1];
                if (r0 >= 0) {
                    float* o = out + (size_t)r0 * N2;
                    if (pcol[2 * ni] >= 0)     o[pcol[2 * ni]]     = acc[mi][ni][0];
                    if (pcol[2 * ni + 1] >= 0) o[pcol[2 * ni + 1]] = acc[mi][ni][1];
                }
                if (r1 >= 0) {
                    float* o = out + (size_t)r1 * N2;
                    if (pcol[2 * ni] >= 0)     o[pcol[2 * ni]]     = acc[mi][ni][2];
                    if (pcol[2 * ni + 1] >= 0) o[pcol[2 * ni + 1]] = acc[mi][ni][3];
                }
            }
        __syncthreads();   // smem stages reused by next tile's prologue
    }
}

// -------------------------------- launch ------------------------------------------
extern "C" void kernel_launch(void* const* d_in, const int* in_sizes, int n_in,
                              void* d_out, int out_size) {
    const float* ft1 = (const float*)d_in[0];
    const float* ft2 = (const float*)d_in[1];
    const void*  ty1 = d_in[2];
    const void*  ty2 = d_in[3];
    float* out = (float*)d_out;

    cudaFuncSetAttribute(cross_mma, cudaFuncAttributeMaxDynamicSharedMemorySize, SMEM_BYTES);
    cudaFuncSetAttribute(same_mma,  cudaFuncAttributeMaxDynamicSharedMemorySize, SMEM_BYTES);

    detect_kernel<<<1, 256>>>((const int*)ty1);
    compact_kernel<<<16, 256>>>(ty1, ty2);
    plan_kernel<<<1, 1>>>();
    convert_kernel<<<2 * N1, 128>>>(ft1, ft2, ty1, ty2);

    dim3 gc(64, 64);
    cross_mma<<<gc, 256, SMEM_BYTES>>>(out);       // writes every element (cross value)
    same_mma<<<1024, 256, SMEM_BYTES>>>(out);      // overwrites same-type pairs (full dot)
}

// round 15
// speedup vs baseline: 2.7489x; 1.4037x over previous
#include <cuda_runtime.h>
#include <cuda_fp16.h>
#include <stdint.h>

#define N1 8192
#define N2 8192
#define D  1024
#define C  128
#define NTY 8
#define KE 1024             // same-type GEMM K (plain fp16, no expansion)
#define KC 128              // cross GEMM K

#define STAGES      3
#define CHUNK_K     64                       // fp16 k per chunk
#define STAGE_HALF  (128 * 128)              // 128 rows x 128B  = 16 KB
#define STAGE_BYTES (2 * STAGE_HALF)         // A + B            = 32 KB
#define SMEM_BYTES  (STAGES * STAGE_BYTES)   // 96 KB -> 2 CTAs/SM

// ---------------- device scratch (static: no runtime allocation) ----------------
__device__ __align__(1024) __half g_ft1p[(size_t)N1 * KE];  // perm order fp16 rows
__device__ __align__(1024) __half g_ft2p[(size_t)N2 * KE];
__device__ __align__(1024) __half g_sl1x[(size_t)N1 * KC];  // orig order slot slices
__device__ __align__(1024) __half g_sl2x[(size_t)N2 * KC];
__device__ int g_perm1[N1], g_perm2[N2];
__device__ int g_start1[NTY], g_cnt1[NTY];
__device__ int g_start2[NTY], g_cnt2[NTY];
__device__ int g_tilePrefix[NTY + 1];
__device__ int g_totalTiles;
__device__ int g_is64;

// ---------------- small PTX helpers (base ISA, compute_103-safe) ----------------
__device__ __forceinline__ uint32_t smem_u32(const void* p) {
    uint32_t a;
    asm("{ .reg .u64 t; cvta.to.shared.u64 t, %1; cvt.u32.u64 %0, t; }" : "=r"(a) : "l"(p));
    return a;
}
__device__ __forceinline__ void cp16(uint32_t s, const void* g) {
    asm volatile("cp.async.cg.shared.global [%0], [%1], 16;" :: "r"(s), "l"(g));
}
#define CP_COMMIT() asm volatile("cp.async.commit_group;" ::: "memory")
#define CP_WAIT1()  asm volatile("cp.async.wait_group 1;" ::: "memory")

__device__ __forceinline__ void ldsm4(uint32_t r[4], uint32_t addr) {
    asm volatile("ldmatrix.sync.aligned.m8n8.x4.shared.b16 {%0,%1,%2,%3}, [%4];"
                 : "=r"(r[0]), "=r"(r[1]), "=r"(r[2]), "=r"(r[3]) : "r"(addr));
}
__device__ __forceinline__ void mma16816(float c[4], const uint32_t a[4],
                                         uint32_t b0, uint32_t b1) {
    asm volatile("mma.sync.aligned.m16n8k16.row.col.f32.f16.f16.f32 "
                 "{%0,%1,%2,%3}, {%4,%5,%6,%7}, {%8,%9}, {%0,%1,%2,%3};"
                 : "+f"(c[0]), "+f"(c[1]), "+f"(c[2]), "+f"(c[3])
                 : "r"(a[0]), "r"(a[1]), "r"(a[2]), "r"(a[3]), "r"(b0), "r"(b1));
}
// swizzled smem address: rows 128B, 16B quads, quad' = quad ^ (row & 7)
__device__ __forceinline__ uint32_t swz(uint32_t base, int row, int quad) {
    return base + row * 128 + ((quad ^ (row & 7)) << 4);
}

// ---------------- dtype detection (int64 vs silently-downgraded int32) ----------
__global__ void detect_kernel(const int* __restrict__ tyraw) {
    __shared__ int sAny;
    if (threadIdx.x == 0) sAny = 0;
    __syncthreads();
    int any = 0;
    for (int i = threadIdx.x; i < 4096; i += blockDim.x) any |= (tyraw[2 * i + 1] != 0);
    if (any) atomicOr(&sAny, 1);
    __syncthreads();
    if (threadIdx.x == 0) g_is64 = sAny ? 0 : 1;
}
__device__ __forceinline__ int load_type(const void* ty, int i, int is64) {
    int t = is64 ? (int)((const long long*)ty)[i] : ((const int*)ty)[i];
    return t & 7;
}

// ---------------- counting sort (stable compaction per type bin) ----------------
__global__ void compact_kernel(const void* __restrict__ ty1, const void* __restrict__ ty2) {
    __shared__ int sTy[N1];
    __shared__ int sBase;
    const int which = blockIdx.x >> 3;
    const int t     = blockIdx.x & 7;
    const void* ty = which ? ty2 : ty1;
    int* perm      = which ? g_perm2 : g_perm1;
    const int n = which ? N2 : N1;
    const int tid = threadIdx.x;
    const int is64 = g_is64;

    if (tid == 0) sBase = 0;
    __syncthreads();
    for (int i = tid; i < n; i += blockDim.x) sTy[i] = load_type(ty, i, is64);
    __syncthreads();
    int lc = 0;
    for (int i = tid; i < n; i += blockDim.x) lc += (sTy[i] < t) ? 1 : 0;
#pragma unroll
    for (int o = 16; o > 0; o >>= 1) lc += __shfl_down_sync(0xffffffffu, lc, o);
    if ((tid & 31) == 0) atomicAdd(&sBase, lc);
    __syncthreads();
    if (tid < 32) {
        int off = sBase;
        for (int base = 0; base < n; base += 32) {
            int i = base + tid;
            int e = (sTy[i] == t) ? 1 : 0;
            unsigned m = __ballot_sync(0xffffffffu, e != 0);
            if (e) perm[off + __popc(m & ((1u << tid) - 1u))] = i;
            off += __popc(m);
        }
        if (tid == 0) {
            if (which) { g_start2[t] = sBase; g_cnt2[t] = off - sBase; }
            else       { g_start1[t] = sBase; g_cnt1[t] = off - sBase; }
        }
    }
}

__global__ void plan_kernel() {
    int tp = 0;
    for (int t = 0; t < NTY; t++) {
        g_tilePrefix[t] = tp;
        tp += ((g_cnt1[t] + 127) >> 7) * ((g_cnt2[t] + 127) >> 7);   // 128x128 tiles
    }
    g_tilePrefix[NTY] = tp;
    g_totalTiles = tp;
}

// ---------------- convert: fp32 -> plain fp16 ------------------------------------
// rel-err model (empirically anchored by R14): dropping B-lo alone gave 2.08e-4;
// full fp16 adds one independent equal term -> ~2.9e-4 << 1e-3.
__global__ void convert_kernel(const float* __restrict__ ft1, const float* __restrict__ ft2,
                               const void* __restrict__ ty1, const void* __restrict__ ty2) {
    const int pos   = blockIdx.x & (N1 - 1);
    const int which = blockIdx.x >> 13;
    const float* ft = which ? ft2 : ft1;
    const void* ty  = which ? ty2 : ty1;
    const int* perm = which ? g_perm2 : g_perm1;
    __half* ftp = which ? g_ft2p : g_ft1p;
    __half* slx = which ? g_sl2x : g_sl1x;
    const int tid  = threadIdx.x;                // 128 threads x 8 k each
    const int orig = perm[pos];
    const int t    = load_type(ty, orig, g_is64);

    const float4* s = (const float4*)(ft + (size_t)orig * D) + tid * 2;
    float4 a = s[0], b = s[1];
    float x[8] = {a.x, a.y, a.z, a.w, b.x, b.y, b.z, b.w};

    unsigned u[4];
#pragma unroll
    for (int j = 0; j < 4; j++) {
        unsigned h0 = __half_as_ushort(__float2half(x[2 * j]));
        unsigned h1 = __half_as_ushort(__float2half(x[2 * j + 1]));
        u[j] = h0 | (h1 << 16);
    }
    uint4 w = make_uint4(u[0], u[1], u[2], u[3]);

    *(uint4*)((char*)ftp + (size_t)pos * (KE * 2) + tid * 16) = w;

    if (tid >= t * 16 && tid < t * 16 + 16)
        *(uint4*)((char*)slx + (size_t)orig * (KC * 2) + (tid - t * 16) * 16) = w;
}

// ---------------- GEMM building blocks (R11/R14-proven config) -------------------
// load one 128x64-fp16 chunk of A and B into a swizzled smem stage (256 threads)
__device__ __forceinline__ void issue_chunk(uint32_t stA, uint32_t stB,
        const char* gA, const char* gB, long strA, long strB,
        long rowA0, long rowB0, long maxA, long maxB, int kOff, int tid) {
    int row = tid >> 1;
    int q0  = (tid & 1) << 2;
    long ra = rowA0 + row; if (ra > maxA) ra = maxA;
    long rb = rowB0 + row; if (rb > maxB) rb = maxB;
    const char* pa = gA + ra * strA + kOff;
    const char* pb = gB + rb * strB + kOff;
#pragma unroll
    for (int i = 0; i < 4; i++) {
        int q = q0 + i;
        cp16(swz(stA, row, q), pa + q * 16);
        cp16(swz(stB, row, q), pb + q * 16);
    }
}

// one 128x128x64 chunk of MMAs for this warp (warp tile 64x32, 8 warps 2x4)
__device__ __forceinline__ void mma_chunk(float acc[4][4][4], uint32_t stA, uint32_t stB,
                                          int wm, int wn, int lane) {
#pragma unroll
    for (int j = 0; j < 4; j++) {            // k16 steps within chunk
        uint32_t a[4][4];
#pragma unroll
        for (int mi = 0; mi < 4; mi++) {
            int row  = wm * 64 + mi * 16 + (lane & 15);
            int quad = 2 * j + (lane >> 4);
            ldsm4(a[mi], swz(stA, row, quad));
        }
        uint32_t b[2][4];
#pragma unroll
        for (int np = 0; np < 2; np++) {
            int row  = wn * 32 + np * 16 + (lane & 7) + ((lane & 16) >> 1);
            int quad = 2 * j + ((lane >> 3) & 1);
            ldsm4(b[np], swz(stB, row, quad));
        }
#pragma unroll
        for (int mi = 0; mi < 4; mi++)
#pragma unroll
            for (int ni = 0; ni < 4; ni++)
                mma16816(acc[mi][ni], a[mi], b[ni >> 1][(ni & 1) * 2],
                         b[ni >> 1][(ni & 1) * 2 + 1]);
    }
}

// ---------------- cross GEMM: out = sl1x @ sl2x^T (all pairs), K=128 -------------
__global__ __launch_bounds__(256)
void cross_mma(float* __restrict__ out) {
    extern __shared__ char smc[];
    uint32_t sb = smem_u32(smc);
    const int tid = threadIdx.x, lane = tid & 31, warp = tid >> 5;
    const int wm = warp & 1, wn = warp >> 1;
    const int bi = blockIdx.y, bj = blockIdx.x;
    const char* gA = (const char*)g_sl1x;
    const char* gB = (const char*)g_sl2x;
    const long strA = KC * 2, strB = KC * 2;
    const long rA0 = (long)bi * 128, rB0 = (long)bj * 128;
    const int NC = KC / CHUNK_K;   // 2

    float acc[4][4][4];
#pragma unroll
    for (int mi = 0; mi < 4; mi++)
#pragma unroll
        for (int ni = 0; ni < 4; ni++)
#pragma unroll
            for (int q = 0; q < 4; q++) acc[mi][ni][q] = 0.f;

    issue_chunk(sb, sb + STAGE_HALF, gA, gB, strA, strB, rA0, rB0, N1 - 1, N2 - 1, 0, tid);
    CP_COMMIT();
    issue_chunk(sb + STAGE_BYTES, sb + STAGE_BYTES + STAGE_HALF, gA, gB, strA, strB,
                rA0, rB0, N1 - 1, N2 - 1, 128, tid);
    CP_COMMIT();

#pragma unroll 1
    for (int c = 0; c < NC; c++) {
        CP_WAIT1();
        __syncthreads();
        int cn = c + 2;
        if (cn < NC) {
            int s = cn % STAGES;
            issue_chunk(sb + s * STAGE_BYTES, sb + s * STAGE_BYTES + STAGE_HALF,
                        gA, gB, strA, strB, rA0, rB0, N1 - 1, N2 - 1, cn * 128, tid);
        }
        CP_COMMIT();
        int s = c % STAGES;
        mma_chunk(acc, sb + s * STAGE_BYTES, sb + s * STAGE_BYTES + STAGE_HALF, wm, wn, lane);
    }

    const int rbase = bi * 128 + wm * 64;
    const int cbase = bj * 128 + wn * 32;
#pragma unroll
    for (int mi = 0; mi < 4; mi++)
#pragma unroll
        for (int ni = 0; ni < 4; ni++) {
            int rr = rbase + mi * 16 + (lane >> 2);
            int cc = cbase + ni * 8 + ((lane & 3) << 1);
            *(float2*)(out + (size_t)rr * N2 + cc) =
                make_float2(acc[mi][ni][0], acc[mi][ni][1]);
            *(float2*)(out + (size_t)(rr + 8) * N2 + cc) =
                make_float2(acc[mi][ni][2], acc[mi][ni][3]);
        }
}

// ---------------- same-type GEMM: full K=1024, permuted rows, scatter ------------
__global__ __launch_bounds__(256)
void same_mma(float* __restrict__ out) {
    extern __shared__ char sms[];
    uint32_t sb = smem_u32(sms);
    const int tid = threadIdx.x, lane = tid & 31, warp = tid >> 5;
    const int wm = warp & 1, wn = warp >> 1;
    const char* gA = (const char*)g_ft1p;
    const char* gB = (const char*)g_ft2p;
    const long strA = KE * 2, strB = KE * 2;
    const int NC = KE / CHUNK_K;   // 16
    const int total = g_totalTiles;

#pragma unroll 1
    for (int tile = blockIdx.x; tile < total; tile += gridDim.x) {
        int t = 0;
        while (tile >= g_tilePrefix[t + 1]) t++;
        const int local = tile - g_tilePrefix[t];
        const int m = g_cnt1[t], n = g_cnt2[t];
        const int gn = (n + 127) >> 7;
        const int mbase = (local / gn) * 128, nbase = (local % gn) * 128;
        const int s1 = g_start1[t], s2 = g_start2[t];
        const long rA0 = s1 + mbase, rB0 = s2 + nbase;

        float acc[4][4][4];
#pragma unroll
        for (int mi = 0; mi < 4; mi++)
#pragma unroll
            for (int ni = 0; ni < 4; ni++)
#pragma unroll
                for (int q = 0; q < 4; q++) acc[mi][ni][q] = 0.f;

        issue_chunk(sb, sb + STAGE_HALF, gA, gB, strA, strB, rA0, rB0, N1 - 1, N2 - 1, 0, tid);
        CP_COMMIT();
        issue_chunk(sb + STAGE_BYTES, sb + STAGE_BYTES + STAGE_HALF, gA, gB, strA, strB,
                    rA0, rB0, N1 - 1, N2 - 1, 128, tid);
        CP_COMMIT();

#pragma unroll 1
        for (int c = 0; c < NC; c++) {
            CP_WAIT1();
            __syncthreads();
            int cn = c + 2;
            if (cn < NC) {
                int s = cn % STAGES;
                issue_chunk(sb + s * STAGE_BYTES, sb + s * STAGE_BYTES + STAGE_HALF,
                            gA, gB, strA, strB, rA0, rB0, N1 - 1, N2 - 1, cn * 128, tid);
            }
            CP_COMMIT();
            int s = c % STAGES;
            mma_chunk(acc, sb + s * STAGE_BYTES, sb + s * STAGE_BYTES + STAGE_HALF, wm, wn, lane);
        }

        // scattered epilogue via perm lookups (bounds-masked)
        int prow[8];
#pragma unroll
        for (int mi = 0; mi < 4; mi++) {
            int pm0 = mbase + wm * 64 + mi * 16 + (lane >> 2);
            prow[2 * mi]     = (pm0 < m)     ? g_perm1[s1 + pm0]     : -1;
            prow[2 * mi + 1] = (pm0 + 8 < m) ? g_perm1[s1 + pm0 + 8] : -1;
        }
        int pcol[8];
#pragma unroll
        for (int ni = 0; ni < 4; ni++) {
            int cn0 = nbase + wn * 32 + ni * 8 + ((lane & 3) << 1);
            pcol[2 * ni]     = (cn0 < n)     ? g_perm2[s2 + cn0]     : -1;
            pcol[2 * ni + 1] = (cn0 + 1 < n) ? g_perm2[s2 + cn0 + 1] : -1;
        }
#pragma unroll
        for (int mi = 0; mi < 4; mi++)
#pragma unroll
            for (int ni = 0; ni < 4; ni++) {
                int r0 = prow[2 * mi], r1 = prow[2 * mi + 1];
                if (r0 >= 0) {
                    float* o = out + (size_t)r0 * N2;
                    if (pcol[2 * ni] >= 0)     o[pcol[2 * ni]]     = acc[mi][ni][0];
                    if (pcol[2 * ni + 1] >= 0) o[pcol[2 * ni + 1]] = acc[mi][ni][1];
                }
                if (r1 >= 0) {
                    float* o = out + (size_t)r1 * N2;
                    if (pcol[2 * ni] >= 0)     o[pcol[2 * ni]]     = acc[mi][ni][2];
                    if (pcol[2 * ni + 1] >= 0) o[pcol[2 * ni + 1]] = acc[mi][ni][3];
                }
            }
        __syncthreads();   // smem stages reused by next tile's prologue
    }
}

// -------------------------------- launch ------------------------------------------
extern "C" void kernel_launch(void* const* d_in, const int* in_sizes, int n_in,
                              void* d_out, int out_size) {
    const float* ft1 = (const float*)d_in[0];
    const float* ft2 = (const float*)d_in[1];
    const void*  ty1 = d_in[2];
    const void*  ty2 = d_in[3];
    float* out = (float*)d_out;

    cudaFuncSetAttribute(cross_mma, cudaFuncAttributeMaxDynamicSharedMemorySize, SMEM_BYTES);
    cudaFuncSetAttribute(same_mma,  cudaFuncAttributeMaxDynamicSharedMemorySize, SMEM_BYTES);

    detect_kernel<<<1, 256>>>((const int*)ty1);
    compact_kernel<<<16, 256>>>(ty1, ty2);
    plan_kernel<<<1, 1>>>();
    convert_kernel<<<2 * N1, 128>>>(ft1, ft2, ty1, ty2);

    dim3 gc(64, 64);
    cross_mma<<<gc, 256, SMEM_BYTES>>>(out);       // writes every element (cross value)
    same_mma<<<1024, 256, SMEM_BYTES>>>(out);      // overwrites same-type pairs (full dot)
}